// round 15
// baseline (speedup 1.0000x reference)
#include <cuda_runtime.h>
#include <cuda_fp16.h>
#include <cstdint>
#include <cstddef>

// ---------------------------------------------------------------------------
// RoutedAllFC round 15: software-pipelined (double-buffered) cp.async staging
// in conv_mma — chunk cc+1 loads overlap chunk cc MMAs. Numerics unchanged
// from r14 (conv2 2-product fp16, conv1/3/4 3-product).
// ---------------------------------------------------------------------------

#define B_   64
#define CH_  160
#define EPS_ 1e-5f

// activations, channel-last fp16 hi/lo splits
__device__ __half g_y1h[B_ * 32 * 32 * CH_];
__device__ __half g_y1l[B_ * 32 * 32 * CH_];
__device__ __half g_y2h[B_ * 16 * 16 * CH_];
__device__ __half g_y2l[B_ * 16 * 16 * CH_];
__device__ __half g_y3h[B_ * 8 * 8 * CH_];
__device__ __half g_y3l[B_ * 8 * 8 * CH_];
// weights fp16 hi/lo
__device__ __half g_w1h[CH_ * 32];
__device__ __half g_w1l[CH_ * 32];
__device__ __half g_w2h[9 * CH_ * CH_];   // [tap][co][ci] (lo unused by conv2)
__device__ __half g_w2l[9 * CH_ * CH_];
__device__ __half g_w3h[9 * CH_ * CH_];
__device__ __half g_w3l[9 * CH_ * CH_];
__device__ __half g_w4h[9 * CH_ * CH_];
__device__ __half g_w4l[9 * CH_ * CH_];
// fp32 tail
__device__ float g_y4[B_ * CH_ * 4 * 4];
__device__ float g_feat[B_ * 2560];
__device__ float g_h1[B_ * 320];
__device__ float g_h2[B_ * 320];

// ---- fp16 split --------------------------------------------------------------
__device__ __forceinline__ void hsplit(float v, __half& h, __half& l) {
    h = __float2half_rn(v);
    l = __float2half_rn(v - __half2float(h));
}

// ---- mma / ldmatrix / cp.async -----------------------------------------------
__device__ __forceinline__ void mma16816(float* c, const unsigned* a,
                                         unsigned b0, unsigned b1) {
    asm("mma.sync.aligned.m16n8k16.row.col.f32.f16.f16.f32 "
        "{%0,%1,%2,%3},{%4,%5,%6,%7},{%8,%9},{%0,%1,%2,%3};"
        : "+f"(c[0]), "+f"(c[1]), "+f"(c[2]), "+f"(c[3])
        : "r"(a[0]), "r"(a[1]), "r"(a[2]), "r"(a[3]), "r"(b0), "r"(b1));
}
__device__ __forceinline__ void ldsm4(unsigned* r, unsigned addr) {
    asm volatile("ldmatrix.sync.aligned.m8n8.x4.shared.b16 {%0,%1,%2,%3}, [%4];"
                 : "=r"(r[0]), "=r"(r[1]), "=r"(r[2]), "=r"(r[3]) : "r"(addr));
}
__device__ __forceinline__ unsigned scvta(const void* p) {
    return (unsigned)__cvta_generic_to_shared(p);
}
__device__ __forceinline__ void cpasync16(unsigned dst, const void* src, int ss) {
    asm volatile("cp.async.cg.shared.global [%0], [%1], 16, %2;"
                 :: "r"(dst), "l"(src), "r"(ss));
}

// ---------------------------------------------------------------------------
// weight pre-splits (fp32 [co][ci][3][3] -> fp16 h/l [tap][co][ci])
// ---------------------------------------------------------------------------
__global__ void __launch_bounds__(256)
pre_w(const float* __restrict__ W2, const float* __restrict__ W3,
      const float* __restrict__ W4,
      __half* __restrict__ O2h, __half* __restrict__ O2l,
      __half* __restrict__ O3h, __half* __restrict__ O3l,
      __half* __restrict__ O4h, __half* __restrict__ O4l) {
    int idx = blockIdx.x * 256 + threadIdx.x;
    if (idx >= 9 * CH_ * CH_) return;
    const float* W = (blockIdx.y == 0) ? W2 : (blockIdx.y == 1) ? W3 : W4;
    __half* Oh = (blockIdx.y == 0) ? O2h : (blockIdx.y == 1) ? O3h : O4h;
    __half* Ol = (blockIdx.y == 0) ? O2l : (blockIdx.y == 1) ? O3l : O4l;
    int tap = idx / (CH_ * CH_);
    int r = idx - tap * (CH_ * CH_);
    int co = r / CH_, ci = r - co * CH_;
    __half h, l;
    hsplit(W[(co * CH_ + ci) * 9 + tap], h, l);
    Oh[idx] = h;
    Ol[idx] = l;
}

__global__ void __launch_bounds__(256)
pre_w1(const float* __restrict__ W, __half* __restrict__ Oh,
       __half* __restrict__ Ol) {
    int idx = blockIdx.x * 256 + threadIdx.x;
    if (idx >= CH_ * 32) return;
    int co = idx >> 5, k = idx & 31;
    __half h, l;
    hsplit((k < 27) ? W[co * 27 + k] : 0.f, h, l);
    Oh[idx] = h;
    Ol[idx] = l;
}

// ---------------------------------------------------------------------------
// conv1: im2col GEMM, one block = one 8x8-prepool tile x ALL 160 co.
// 3-product fp16. (unchanged from r14)
// ---------------------------------------------------------------------------
__global__ void __launch_bounds__(128)
conv1_mma(const float* __restrict__ x,
          const __half* __restrict__ Wh, const __half* __restrict__ Wl,
          const float* __restrict__ bias,
          __half* __restrict__ Oh, __half* __restrict__ Ol) {
    constexpr int KP = 40;
    __shared__ float s_halo[3][10][10];
    __shared__ alignas(16) __half s_ah[64][KP];
    __shared__ alignas(16) __half s_al[64][KP];
    __shared__ alignas(16) __half s_wh[160][KP];
    __shared__ alignas(16) __half s_wl[160][KP];

    const int tid = threadIdx.x;
    const int wrp = tid >> 5, lane = tid & 31;
    const int nimg = blockIdx.y;
    const int ty = blockIdx.x >> 3, tx = blockIdx.x & 7;
    const int py0 = ty * 8, px0 = tx * 8;

    for (int idx = tid; idx < 300; idx += 128) {
        int ci = idx / 100, rem = idx - ci * 100;
        int ly = rem / 10, lx = rem - ly * 10;
        int gy = py0 - 1 + ly, gx = px0 - 1 + lx;
        float v = 0.f;
        if ((unsigned)gy < 64u && (unsigned)gx < 64u)
            v = x[(((size_t)nimg * 3 + ci) * 64 + gy) * 64 + gx];
        s_halo[ci][ly][lx] = v;
    }
    for (int idx = tid; idx < 640; idx += 128) {
        int nn = idx >> 2, q = idx & 3;
        *(uint4*)&s_wh[nn][q * 8] = *(const uint4*)(Wh + nn * 32 + q * 8);
        *(uint4*)&s_wl[nn][q * 8] = *(const uint4*)(Wl + nn * 32 + q * 8);
    }
    __syncthreads();

    for (int idx = tid; idx < 2048; idx += 128) {
        int m = idx >> 5, k = idx & 31;
        int yy = m >> 3, xx = m & 7;
        float v = 0.f;
        if (k < 27) {
            int ci = k / 9, tap = k - ci * 9;
            int ky = tap / 3, kx = tap - ky * 3;
            v = s_halo[ci][yy + ky][xx + kx];
        }
        __half h, l;
        hsplit(v, h, l);
        s_ah[m][k] = h;
        s_al[m][k] = l;
    }
    __syncthreads();

    const int r1 = lane >> 2;
    const int kb = (lane & 3) * 2;
    const int seg = lane >> 3, lx8 = lane & 7;
    const unsigned a_h_base = scvta(&s_ah[16 * wrp + (seg & 1) * 8 + lx8][(seg >> 1) * 8]);
    const unsigned a_l_base = scvta(&s_al[16 * wrp + (seg & 1) * 8 + lx8][(seg >> 1) * 8]);
    const int nrow0 = 8 * (seg >> 1) + lx8;
    const int bk0 = (seg & 1) * 8;
    const unsigned b_h_base = scvta(&s_wh[nrow0][bk0]);
    const unsigned b_l_base = scvta(&s_wl[nrow0][bk0]);

    float acc[20][4];
#pragma unroll
    for (int f = 0; f < 20; f++)
#pragma unroll
        for (int q = 0; q < 4; q++) acc[f][q] = 0.f;

#pragma unroll
    for (int ks = 0; ks < 2; ks++) {
        unsigned ah[4], al[4];
        ldsm4(ah, a_h_base + ks * 32);
        ldsm4(al, a_l_base + ks * 32);
#pragma unroll
        for (int fp = 0; fp < 20; fp += 2) {
            const unsigned boff = (unsigned)(fp * (8 * KP * 2) + ks * 32);
            unsigned bh[4], bl[4];
            ldsm4(bh, b_h_base + boff);
            ldsm4(bl, b_l_base + boff);
            mma16816(acc[fp], ah, bh[0], bh[1]);
            mma16816(acc[fp], al, bh[0], bh[1]);
            mma16816(acc[fp], ah, bl[0], bl[1]);
            mma16816(acc[fp + 1], ah, bh[2], bh[3]);
            mma16816(acc[fp + 1], al, bh[2], bh[3]);
            mma16816(acc[fp + 1], ah, bl[2], bl[3]);
        }
    }

    const int Py = py0 / 2 + wrp;
    const int Px = px0 / 2 + (r1 >> 1);
    const bool writer = ((r1 & 1) == 0);
#pragma unroll
    for (int f = 0; f < 20; f++) {
        int ch = f * 8 + kb;
        float v0 = fmaxf(acc[f][0], acc[f][2]);
        float v1 = fmaxf(acc[f][1], acc[f][3]);
        float o0 = fmaxf(v0, __shfl_xor_sync(0xffffffffu, v0, 4));
        float o1 = fmaxf(v1, __shfl_xor_sync(0xffffffffu, v1, 4));
        if (writer) {
            o0 = fmaxf(o0 + bias[ch], 0.f);
            o1 = fmaxf(o1 + bias[ch + 1], 0.f);
            size_t a = (((size_t)nimg * 32 + Py) * 32 + Px) * CH_ + ch;
            __half h0, l0, h1, l1;
            hsplit(o0, h0, l0);
            hsplit(o1, h1, l1);
            *(__half2*)(Oh + a) = __halves2half2(h0, h1);
            *(__half2*)(Ol + a) = __halves2half2(l0, l1);
        }
    }
}

// ---------------------------------------------------------------------------
// Tensor-core conv3x3+bias+ReLU+maxpool2, IMGS images/block, NPROD in {2,3},
// DOUBLE-BUFFERED cp.async pipeline: chunk cc+1 in flight during chunk cc MMA.
// ---------------------------------------------------------------------------
template <int PP, int IMGS, int NPROD, bool OUT_CL>
__global__ void __launch_bounds__(128 * IMGS)
conv_mma(const __half* __restrict__ Ah, const __half* __restrict__ Al,
         const __half* __restrict__ Wth, const __half* __restrict__ Wtl,
         const float* __restrict__ bias,
         __half* __restrict__ Oh, __half* __restrict__ Ol,
         float* __restrict__ Ocf) {
    constexpr int CIC = 32;
    constexpr int KP = 40;
    constexpr int NCH = CH_ / CIC;   // 5
    constexpr int PPo = PP / 2;
    constexpr int TX = PP / 8;
    constexpr int T = 128 * IMGS;
    constexpr int A_ELEMS = IMGS * 100 * KP;
    constexpr int W_ELEMS = 9 * 32 * KP;
    constexpr int NW = (NPROD == 3) ? 2 : 1;
    constexpr int BUFE = 2 * A_ELEMS + NW * W_ELEMS;   // elems per buffer

    extern __shared__ __align__(16) __half smem[];

    const int tid = threadIdx.x;
    const int wrp = tid >> 5, lane = tid & 31;
    const int im = wrp >> 2, w4 = wrp & 3;
    const int img0 = blockIdx.z * IMGS;
    const int nb0 = blockIdx.y * 32;
    const int ty = blockIdx.x / TX, tx = blockIdx.x % TX;
    const int py0 = ty * 8, px0 = tx * 8;

    const int r1 = lane >> 2;
    const int kb = (lane & 3) * 2;
    const int seg = lane >> 3, lx8 = lane & 7;
    const int ay = 2 * w4 + (seg & 1);
    const int akoff = (seg >> 1) * 8;
    const int nrow0 = 8 * (seg >> 1) + lx8;
    const int bk0 = (seg & 1) * 8;

    // fragment base addresses in buffer 0; buffer 1 adds BUFE*2 bytes
    const unsigned a_h0 = scvta(smem + (im * 100 + ay * 10 + lx8) * KP + akoff);
    const unsigned a_l0 = a_h0 + A_ELEMS * 2;
    const unsigned b_h0 = scvta(smem + 2 * A_ELEMS + nrow0 * KP + bk0);
    const unsigned b_l0 = b_h0 + W_ELEMS * 2;

    // staging of one chunk into buffer b
    auto stage = [&](int cc, int b) {
        __half* d_ah = smem + b * BUFE;
        __half* d_al = d_ah + A_ELEMS;
        __half* d_wh = d_al + A_ELEMS;
        __half* d_wl = d_wh + W_ELEMS;
        for (int idx = tid; idx < IMGS * 400; idx += T) {
            int aim = idx / 400, rem = idx - aim * 400;
            int p = rem >> 2, q = rem & 3;
            int ly = p / 10, lx = p - ly * 10;
            int gy = py0 - 1 + ly, gx = px0 - 1 + lx;
            bool ok = (unsigned)gy < (unsigned)PP && (unsigned)gx < (unsigned)PP;
            size_t g = ok ? ((((size_t)(img0 + aim) * PP + gy) * PP + gx) * CH_ +
                             cc * CIC + q * 8)
                          : 0;
            int ss = ok ? 16 : 0;
            int base = (aim * 100 + ly * 10 + lx) * KP + q * 8;
            cpasync16(scvta(d_ah + base), Ah + g, ss);
            cpasync16(scvta(d_al + base), Al + g, ss);
        }
        for (int idx = tid; idx < 1152; idx += T) {
            int tap = idx >> 7, rem = idx & 127;
            int nn = rem >> 2, q = rem & 3;
            size_t g = ((size_t)tap * CH_ + nb0 + nn) * CH_ + cc * CIC + q * 8;
            int base = (tap * 32 + nn) * KP + q * 8;
            cpasync16(scvta(d_wh + base), Wth + g, 16);
            if (NPROD == 3)
                cpasync16(scvta(d_wl + base), Wtl + g, 16);
        }
    };

    float acc[4][4];
#pragma unroll
    for (int f = 0; f < 4; f++)
#pragma unroll
        for (int q = 0; q < 4; q++) acc[f][q] = 0.f;

    // prologue: stage chunk 0 into buffer 0
    stage(0, 0);
    asm volatile("cp.async.commit_group;");

    for (int cc = 0; cc < NCH; cc++) {
        __syncthreads();   // compute(cc-1) done before overwriting its buffer's twin
        if (cc + 1 < NCH) {
            stage(cc + 1, (cc + 1) & 1);
            asm volatile("cp.async.commit_group;");
            asm volatile("cp.async.wait_group 1;");   // chunk cc landed
        } else {
            asm volatile("cp.async.wait_group 0;");
        }
        __syncthreads();   // staged chunk cc visible to all warps

        const unsigned bo = (unsigned)((cc & 1) * BUFE * 2);
#pragma unroll
        for (int tap = 0; tap < 9; tap++) {
            const int ky = tap / 3, kx = tap % 3;
#pragma unroll
            for (int ks = 0; ks < 2; ks++) {
                const unsigned aoff = (unsigned)((ky * 10 + kx) * (KP * 2) + ks * 32) + bo;
                unsigned ah[4], al[4];
                ldsm4(ah, a_h0 + aoff);
                ldsm4(al, a_l0 + aoff);
#pragma unroll
                for (int fp = 0; fp < 4; fp += 2) {
                    const unsigned boff =
                        (unsigned)(tap * (32 * KP * 2) + fp * (8 * KP * 2) + ks * 32) + bo;
                    unsigned bh[4];
                    ldsm4(bh, b_h0 + boff);
                    mma16816(acc[fp], ah, bh[0], bh[1]);
                    mma16816(acc[fp], al, bh[0], bh[1]);
                    mma16816(acc[fp + 1], ah, bh[2], bh[3]);
                    mma16816(acc[fp + 1], al, bh[2], bh[3]);
                    if (NPROD == 3) {
                        unsigned bl[4];
                        ldsm4(bl, b_l0 + boff);
                        mma16816(acc[fp], ah, bl[0], bl[1]);
                        mma16816(acc[fp + 1], ah, bl[2], bl[3]);
                    }
                }
            }
        }
    }

    const int nimg = img0 + im;
    const int Py = py0 / 2 + w4;
    const int Px = px0 / 2 + (r1 >> 1);
    const bool writer = ((r1 & 1) == 0);
#pragma unroll
    for (int f = 0; f < 4; f++) {
        int ch = nb0 + f * 8 + kb;
        float v0 = fmaxf(acc[f][0], acc[f][2]);
        float v1 = fmaxf(acc[f][1], acc[f][3]);
        float o0 = fmaxf(v0, __shfl_xor_sync(0xffffffffu, v0, 4));
        float o1 = fmaxf(v1, __shfl_xor_sync(0xffffffffu, v1, 4));
        if (writer) {
            o0 = fmaxf(o0 + bias[ch], 0.f);
            o1 = fmaxf(o1 + bias[ch + 1], 0.f);
            if (OUT_CL) {
                size_t a = (((size_t)nimg * PPo + Py) * PPo + Px) * CH_ + ch;
                __half h0, l0, h1, l1;
                hsplit(o0, h0, l0);
                hsplit(o1, h1, l1);
                *(__half2*)(Oh + a) = __halves2half2(h0, h1);
                *(__half2*)(Ol + a) = __halves2half2(l0, l1);
            } else {
                size_t a = (((size_t)nimg * CH_ + ch) * PPo + Py) * PPo + Px;
                Ocf[a] = o0;
                Ocf[a + (size_t)PPo * PPo] = o1;
            }
        }
    }
}

// ---------------------------------------------------------------------------
// BatchNorm (batch stats) + affine + flatten.
// ---------------------------------------------------------------------------
__global__ void __launch_bounds__(256)
bn_flatten(const float* __restrict__ y4, const float* __restrict__ gamma,
           const float* __restrict__ beta, float* __restrict__ feat) {
    int c = blockIdx.x, tid = threadIdx.x;
    int i0 = tid * 4;
    int n = i0 >> 4, hw = i0 & 15;
    float4 v = *(const float4*)(y4 + (((size_t)n * 160 + c) << 4) + hw);
    float s = v.x + v.y + v.z + v.w;
    float q = v.x * v.x + v.y * v.y + v.z * v.z + v.w * v.w;
#pragma unroll
    for (int off = 16; off; off >>= 1) {
        s += __shfl_xor_sync(0xffffffffu, s, off);
        q += __shfl_xor_sync(0xffffffffu, q, off);
    }
    __shared__ float rs[8], rq[8];
    __shared__ float s_scale, s_shift;
    int w = tid >> 5, lane = tid & 31;
    if (!lane) { rs[w] = s; rq[w] = q; }
    __syncthreads();
    if (tid == 0) {
        float S = 0.f, Q = 0.f;
#pragma unroll
        for (int j = 0; j < 8; j++) { S += rs[j]; Q += rq[j]; }
        float mean = S * (1.f / 1024.f);
        float var = Q * (1.f / 1024.f) - mean * mean;
        float r = rsqrtf(var + EPS_);
        float g = gamma[c] * r;
        s_scale = g;
        s_shift = beta[c] - mean * g;
    }
    __syncthreads();
    float g = s_scale, b = s_shift;
    float4 o = make_float4(v.x * g + b, v.y * g + b, v.z * g + b, v.w * g + b);
    *(float4*)(feat + (size_t)n * 2560 + c * 16 + hw) = o;
}

// ---------------------------------------------------------------------------
// Routed linear: warp per output element.
// ---------------------------------------------------------------------------
template <bool RELU>
__global__ void __launch_bounds__(256)
fc_routed(const float* __restrict__ X, const float* __restrict__ Wb,
          const float* __restrict__ Bb, const int* __restrict__ act,
          float* __restrict__ Y, int IN, int OD) {
    int n = blockIdx.y;
    int w = threadIdx.x >> 5, lane = threadIdx.x & 31;
    int o = blockIdx.x * (blockDim.x >> 5) + w;
    if (o >= OD) return;
    int e = act[n];
    const float* wr = Wb + ((size_t)e * OD + o) * IN;
    const float* xr = X + (size_t)n * IN;
    float s = 0.f;
    for (int i = lane * 4; i < IN; i += 128) {
        float4 a = *(const float4*)(wr + i);
        float4 b = *(const float4*)(xr + i);
        s += a.x * b.x + a.y * b.y + a.z * b.z + a.w * b.w;
    }
#pragma unroll
    for (int off = 16; off; off >>= 1) s += __shfl_xor_sync(0xffffffffu, s, off);
    if (!lane) {
        float v = s + Bb[(size_t)e * OD + o];
        if (RELU) v = fmaxf(v, 0.f);
        Y[(size_t)n * OD + o] = v;
    }
}

// ---------------------------------------------------------------------------
extern "C" void kernel_launch(void* const* d_in, const int* in_sizes, int n_in,
                              void* d_out, int out_size) {
    const float* x   = (const float*)d_in[0];
    const int* a1    = (const int*)d_in[1];
    const int* a2    = (const int*)d_in[2];
    const int* a3    = (const int*)d_in[3];
    const float* W1  = (const float*)d_in[4];
    const float* b1  = (const float*)d_in[5];
    const float* W2  = (const float*)d_in[6];
    const float* b2  = (const float*)d_in[7];
    const float* W3  = (const float*)d_in[8];
    const float* b3  = (const float*)d_in[9];
    const float* W4  = (const float*)d_in[10];
    const float* b4  = (const float*)d_in[11];
    const float* gam = (const float*)d_in[12];
    const float* bet = (const float*)d_in[13];
    const float* E1W = (const float*)d_in[14];
    const float* E1b = (const float*)d_in[15];
    const float* E2W = (const float*)d_in[16];
    const float* E2b = (const float*)d_in[17];
    const float* E3W = (const float*)d_in[18];
    const float* E3b = (const float*)d_in[19];
    float* out = (float*)d_out;

    __half *y1h, *y1l, *y2h, *y2l, *y3h, *y3l;
    __half *w1h, *w1l, *w2h, *w2l, *w3h, *w3l, *w4h, *w4l;
    float *y4, *feat, *h1, *h2;
    cudaGetSymbolAddress((void**)&y1h, g_y1h);
    cudaGetSymbolAddress((void**)&y1l, g_y1l);
    cudaGetSymbolAddress((void**)&y2h, g_y2h);
    cudaGetSymbolAddress((void**)&y2l, g_y2l);
    cudaGetSymbolAddress((void**)&y3h, g_y3h);
    cudaGetSymbolAddress((void**)&y3l, g_y3l);
    cudaGetSymbolAddress((void**)&w1h, g_w1h);
    cudaGetSymbolAddress((void**)&w1l, g_w1l);
    cudaGetSymbolAddress((void**)&w2h, g_w2h);
    cudaGetSymbolAddress((void**)&w2l, g_w2l);
    cudaGetSymbolAddress((void**)&w3h, g_w3h);
    cudaGetSymbolAddress((void**)&w3l, g_w3l);
    cudaGetSymbolAddress((void**)&w4h, g_w4h);
    cudaGetSymbolAddress((void**)&w4l, g_w4l);
    cudaGetSymbolAddress((void**)&y4, g_y4);
    cudaGetSymbolAddress((void**)&feat, g_feat);
    cudaGetSymbolAddress((void**)&h1, g_h1);
    cudaGetSymbolAddress((void**)&h2, g_h2);

    // double-buffered dynamic smem sizes (bytes)
    constexpr int SMEM_C2 = 2 * (2 * (4 * 100 * 40) + 9 * 32 * 40) * 2;        // 174080
    constexpr int SMEM_C3 = 2 * (2 * (4 * 100 * 40) + 2 * (9 * 32 * 40)) * 2;  // 220160
    constexpr int SMEM_C4 = 2 * (2 * (2 * 100 * 40) + 2 * (9 * 32 * 40)) * 2;  // 156160
    static bool attr_set = false;
    if (!attr_set) {
        cudaFuncSetAttribute(conv_mma<32, 4, 2, true>,
                             cudaFuncAttributeMaxDynamicSharedMemorySize, SMEM_C2);
        cudaFuncSetAttribute(conv_mma<16, 4, 3, true>,
                             cudaFuncAttributeMaxDynamicSharedMemorySize, SMEM_C3);
        cudaFuncSetAttribute(conv_mma<8, 2, 3, false>,
                             cudaFuncAttributeMaxDynamicSharedMemorySize, SMEM_C4);
        attr_set = true;
    }

    // weight pre-splits
    pre_w<<<dim3((9 * CH_ * CH_ + 255) / 256, 3), 256>>>(
        W2, W3, W4, w2h, w2l, w3h, w3l, w4h, w4l);
    pre_w1<<<(CH_ * 32 + 255) / 256, 256>>>(W1, w1h, w1l);

    // conv1: all-co im2col GEMM, 3-product
    conv1_mma<<<dim3(64, 64), 128>>>(x, w1h, w1l, b1, y1h, y1l);
    // conv2: 4 images/block, 2-product, pipelined
    conv_mma<32, 4, 2, true><<<dim3(16, 5, 16), 512, SMEM_C2>>>(
        y1h, y1l, w2h, nullptr, b2, y2h, y2l, nullptr);
    // conv3: 4 images/block, 3-product, pipelined
    conv_mma<16, 4, 3, true><<<dim3(4, 5, 16), 512, SMEM_C3>>>(
        y2h, y2l, w3h, w3l, b3, y3h, y3l, nullptr);
    // conv4: 2 images/block, 3-product, pipelined, fp32 chan-first out
    conv_mma<8, 2, 3, false><<<dim3(1, 5, 32), 256, SMEM_C4>>>(
        y3h, y3l, w4h, w4l, b4, nullptr, nullptr, y4);

    bn_flatten<<<160, 256>>>(y4, gam, bet, feat);

    fc_routed<true ><<<dim3(40, 64), 256>>>(feat, E1W, E1b, a1, h1, 2560, 320);
    fc_routed<true ><<<dim3(40, 64), 256>>>(h1,   E2W, E2b, a2, h2, 320, 320);
    fc_routed<false><<<dim3(2, 64),  256>>>(h2,   E3W, E3b, a3, out, 320, 10);
}